// round 8
// baseline (speedup 1.0000x reference)
#include <cuda_runtime.h>
#include <math.h>

// Fixed problem shapes (B=256, R=512, D=64, N=100000, E=3.2M)
#define RR   512
#define DD   64
#define BB   256
#define DIN  132          // 2*DD + 4
#define TBL  1024         // hash table slots (load factor <= 0.25)
#define TBLM (TBL - 1)
#define EMPTY_KEY (-1)
#define NCHUNK 16         // gather chunks (64 threads each) in k_fuse
#define NREP 32           // histogram replicas (128B stride per bin)

// Scratch (device globals: no allocation allowed in kernel_launch)
__device__ int g_Mq[BB * RR];           // per-representative-b relation counts
__device__ int g_relc2[RR * NREP];      // replicated relation histogram (L2 atomics)

__device__ __forceinline__ unsigned hash_ent(int x) {
    return ((unsigned)x * 2654435761u) >> 16;
}

// ---------------------------------------------------------------- init
// Pure clear, 1 int4 per thread: (512KB + 64KB) / 16B = 36864+... total
// (BB*RR + RR*NREP)/4 = (131072 + 4096) int4 = 135168 -> 528 blocks x 256.
__global__ __launch_bounds__(256) void k_init() {
    int gid = blockIdx.x * 256 + threadIdx.x;
    if (gid < BB * RR / 4)
        ((int4*)g_Mq)[gid] = make_int4(0, 0, 0, 0);
    else if (gid < (BB * RR + RR * NREP) / 4)
        ((int4*)g_relc2)[gid - BB * RR / 4] = make_int4(0, 0, 0, 0);
}

// ---------------------------------------------------------------- edge scan
// Histogram via replicated global REDG (no SMEM atomic on the hot path);
// Mq via SMEM hash probe + rare global atomic. Probe loops bounded.
__device__ __forceinline__ void lookup_add(int e, int y,
                                           const int* __restrict__ skeys,
                                           const int* __restrict__ svals) {
    unsigned s = hash_ent(e) & TBLM;
    #pragma unroll 1
    for (int p = 0; p < TBL; p++) {
        int k = skeys[s];
        if (k == e) { atomicAdd(&g_Mq[svals[s] * RR + y], 1); return; }
        if (k == EMPTY_KEY) return;
        s = (s + 1) & TBLM;
    }
}

__device__ __forceinline__ void process_edge(int h, int t, int y, int rep,
                                             const int* __restrict__ skeys,
                                             const int* __restrict__ svals) {
    atomicAdd(&g_relc2[y * NREP + rep], 1);   // return unused -> REDG
    lookup_add(h, y, skeys, svals);
    if (t != h) lookup_add(t, y, skeys, svals);   // self-loop counted once
}

__global__ __launch_bounds__(256) void k_edges(const int* __restrict__ heads,
                                               const int* __restrict__ tails,
                                               const int* __restrict__ types,
                                               const int* __restrict__ qent,
                                               int B, int E) {
    __shared__ int skeys[TBL];
    __shared__ int svals[TBL];
    int tid = threadIdx.x;
    int rep = blockIdx.x & (NREP - 1);
    for (int j = tid; j < TBL; j += 256) { skeys[j] = EMPTY_KEY; svals[j] = 0x7FFFFFFF; }
    __syncthreads();
    // build hash from qent (parallel CASes, dedup via min-b); bounded probes
    for (int q = tid; q < B; q += 256) {
        int ent = qent[q];
        unsigned s = hash_ent(ent) & TBLM;
        #pragma unroll 1
        for (int p = 0; p < TBL; p++) {
            int prev = atomicCAS(&skeys[s], EMPTY_KEY, ent);
            if (prev == EMPTY_KEY || prev == ent) {
                atomicMin(&svals[s], q);   // representative = min b
                break;
            }
            s = (s + 1) & TBLM;
        }
    }
    __syncthreads();

    const int4* h4 = (const int4*)heads;
    const int4* t4 = (const int4*)tails;
    const int4* y4 = (const int4*)types;
    int E4 = E >> 2;
    int gid = blockIdx.x * blockDim.x + tid;
    int stride = gridDim.x * blockDim.x;
    for (int i = gid; i < E4; i += stride) {
        int4 h = h4[i];
        int4 t = t4[i];
        int4 y = y4[i];
        process_edge(h.x, t.x, y.x, rep, skeys, svals);
        process_edge(h.y, t.y, y.y, rep, skeys, svals);
        process_edge(h.z, t.z, y.z, rep, skeys, svals);
        process_edge(h.w, t.w, y.w, rep, skeys, svals);
    }
    if (blockIdx.x == 0 && tid < (E & 3)) {
        int e = (E4 << 2) + tid;
        process_edge(heads[e], tails[e], types[e], rep, skeys, svals);
    }
}

// ---------------------------------------------------------------- fused epilogue
// One block of 1024 threads per b: rep scan + Mq row -> deg + hist-replica
// sum + gather (16 chunks x 64 d) -> fixed-order reduce -> MLP.
__global__ __launch_bounds__(1024) void k_fuse(
    const float* __restrict__ rel_emb,   // [B, R, D]
    const int* __restrict__ qrels,
    const int* __restrict__ qent,
    const float* __restrict__ W1, const float* __restrict__ b1,
    const float* __restrict__ W2, const float* __restrict__ b2,
    const float* __restrict__ W3, const float* __restrict__ b3,
    const float* __restrict__ W4, const float* __restrict__ b4,
    float* __restrict__ out, int B, int E, float density) {
    int b = blockIdx.x;
    int tid = threadIdx.x;
    int lane = tid & 31;

    __shared__ float scnt[RR];
    __shared__ float spart[NCHUNK * DD];
    __shared__ float sx[DIN];
    __shared__ float sw[2][DD];
    __shared__ float sh1[DD];
    __shared__ float sh2[32];
    __shared__ float sg[16];
    __shared__ int sdeg;
    __shared__ int srep;
    __shared__ int srelc;

    if (tid == 0) { sdeg = 0; srep = 0x7FFFFFFF; }
    __syncthreads();
    // rep = min j with qent[j] == qent[b]  (deterministic, direct scan)
    int myent = qent[b];
    if (tid < B && qent[tid] == myent) atomicMin(&srep, tid);
    __syncthreads();
    int rep = srep;
    int qr = qrels[b];

    if (tid < RR) {
        int c = g_Mq[rep * RR + tid];
        scnt[tid] = (float)c;
        #pragma unroll
        for (int o = 16; o; o >>= 1) c += __shfl_down_sync(0xffffffffu, c, o);
        if (lane == 0) atomicAdd(&sdeg, c); // integer: deterministic
    } else if (tid >= 512 && tid < 544) {
        // warp 16: sum the NREP histogram replicas for bin qr
        int v = g_relc2[qr * NREP + (tid - 512)];
        #pragma unroll
        for (int o = 16; o; o >>= 1) v += __shfl_down_sync(0xffffffffu, v, o);
        if (lane == 0) srelc = v;           // single writer
    }
    __syncthreads();

    // gather: chunk = tid>>6 handles r in [chunk*32, chunk*32+32)
    {
        int d = tid & 63;
        int ch = tid >> 6;
        const float* base = rel_emb + (size_t)b * RR * DD + d;
        float acc = 0.f;
        #pragma unroll
        for (int j = 0; j < 32; j++) {
            int r = ch * 32 + j;
            float cw = scnt[r];             // uniform across the 64-thread group
            if (cw != 0.0f) acc = fmaf(cw, base[(size_t)r * DD], acc);
        }
        spart[ch * DD + d] = acc;
    }

    float deg = (float)sdeg;
    float inv = 1.0f / fmaxf(deg, 1.0f);
    if (tid < DD)
        sx[tid] = rel_emb[((size_t)b * RR + qr) * DD + tid];
    __syncthreads();
    if (tid < DD) {
        const float* p = spart + tid;
        float s = 0.f;
        #pragma unroll
        for (int c = 0; c < NCHUNK; c++) s += p[c * DD];   // fixed order
        sx[DD + tid] = s * inv;
    }
    if (tid == 0) {
        float freq = fminf((float)srelc / (float)E, 1.0f);
        float degn = fminf(deg / (float)E, 1.0f);
        sx[128] = freq;
        sx[129] = degn;
        sx[130] = freq;
        sx[131] = density;
    }
    __syncthreads();

    // W1: 132 -> 64, input range split across 2 half-groups, 4 accs each
    if (tid < 128) {
        int o = tid & 63;
        int h = tid >> 6;
        int i0 = h * 66;
        float a0 = 0.f, a1 = 0.f, a2 = 0.f, a3 = 0.f;
        const float* wcol = W1 + o;
        #pragma unroll
        for (int i = 0; i < 64; i += 4) {
            a0 = fmaf(sx[i0 + i],     wcol[(i0 + i) * 64],     a0);
            a1 = fmaf(sx[i0 + i + 1], wcol[(i0 + i + 1) * 64], a1);
            a2 = fmaf(sx[i0 + i + 2], wcol[(i0 + i + 2) * 64], a2);
            a3 = fmaf(sx[i0 + i + 3], wcol[(i0 + i + 3) * 64], a3);
        }
        a0 = fmaf(sx[i0 + 64], wcol[(i0 + 64) * 64], a0);
        a1 = fmaf(sx[i0 + 65], wcol[(i0 + 65) * 64], a1);
        sw[h][o] = (a0 + a1) + (a2 + a3);
    }
    __syncthreads();
    if (tid < DD)
        sh1[tid] = fmaxf(b1[tid] + sw[0][tid] + sw[1][tid], 0.0f);
    __syncthreads();
    if (tid < 32) {
        float a0 = b2[tid], a1 = 0.f, a2 = 0.f, a3 = 0.f;
        #pragma unroll
        for (int i = 0; i < 64; i += 4) {
            a0 = fmaf(sh1[i],     W2[i * 32 + tid],       a0);
            a1 = fmaf(sh1[i + 1], W2[(i + 1) * 32 + tid], a1);
            a2 = fmaf(sh1[i + 2], W2[(i + 2) * 32 + tid], a2);
            a3 = fmaf(sh1[i + 3], W2[(i + 3) * 32 + tid], a3);
        }
        sh2[tid] = fmaxf((a0 + a1) + (a2 + a3), 0.0f);
    }
    __syncthreads();
    if (tid < 16) {
        float a0 = b3[tid], a1 = 0.f;
        #pragma unroll
        for (int i = 0; i < 32; i += 2) {
            a0 = fmaf(sh2[i],     W3[i * 16 + tid],       a0);
            a1 = fmaf(sh2[i + 1], W3[(i + 1) * 16 + tid], a1);
        }
        sg[tid] = fmaxf(a0 + a1, 0.0f);
    }
    __syncthreads();
    if (tid == 0) {
        float acc = b4[0];
        #pragma unroll
        for (int i = 0; i < 16; i++) acc = fmaf(sg[i], W4[i], acc);
        out[b] = 1.0f / (1.0f + expf(-acc));
    }
}

// ---------------------------------------------------------------- launch
extern "C" void kernel_launch(void* const* d_in, const int* in_sizes, int n_in,
                              void* d_out, int out_size) {
    const float* rel_emb = (const float*)d_in[0];
    const int*   qrels   = (const int*)d_in[1];
    const int*   qent    = (const int*)d_in[2];
    const int*   eidx    = (const int*)d_in[3];
    const int*   etype   = (const int*)d_in[4];
    const float* W1 = (const float*)d_in[n_in - 8];
    const float* b1 = (const float*)d_in[n_in - 7];
    const float* W2 = (const float*)d_in[n_in - 6];
    const float* b2 = (const float*)d_in[n_in - 5];
    const float* W3 = (const float*)d_in[n_in - 4];
    const float* b3 = (const float*)d_in[n_in - 3];
    const float* W4 = (const float*)d_in[n_in - 2];
    const float* b4 = (const float*)d_in[n_in - 1];

    int B = in_sizes[1];          // 256
    int E = in_sizes[4];          // 3,200,000
    const int* heads = eidx;
    const int* tails = eidx + E;

    double Nd = 100000.0;         // fixed problem
    float density = (float)fmin((double)E / (Nd * Nd), 1.0);

    k_init<<<(BB * RR + RR * NREP) / 4 / 256, 256>>>();
    k_edges<<<592, 256>>>(heads, tails, etype, qent, B, E);
    k_fuse<<<B, 1024>>>(rel_emb, qrels, qent,
                        W1, b1, W2, b2, W3, b3, W4, b4,
                        (float*)d_out, B, E, density);
}

// round 10
// speedup vs baseline: 1.4778x; 1.4778x over previous
#include <cuda_runtime.h>
#include <math.h>

// Fixed problem shapes (B=256, R=512, D=64, N=100000, E=3.2M)
#define RR   512
#define DD   64
#define BB   256
#define DIN  132          // 2*DD + 4
#define TBL  1024         // hash table slots (load factor <= 0.25)
#define TBLM (TBL - 1)
#define EMPTY_KEY (-1)
#define NCHUNK 16         // gather chunks (64 threads each) in k_fuse
#define EGRID 1184        // edge blocks: 8 per SM on 148 SMs

// Scratch (device globals: no allocation allowed in kernel_launch)
__device__ int g_Mq[BB * RR];     // per-representative-b relation counts
__device__ int g_relc[RR];        // global relation histogram

__device__ __forceinline__ unsigned hash_ent(int x) {
    return ((unsigned)x * 2654435761u) >> 16;
}

// ---------------------------------------------------------------- init
// Pure clear, fully parallel, no serial phases.
__global__ __launch_bounds__(256) void k_init() {
    int gid = blockIdx.x * 256 + threadIdx.x;
    if (gid < BB * RR / 4)
        ((int4*)g_Mq)[gid] = make_int4(0, 0, 0, 0);
    if (gid < RR) g_relc[gid] = 0;
}

// ---------------------------------------------------------------- edge scan
// Per-block SMEM hash (key,val packed as int2) + SMEM-atomic histogram.
// Probe loops bounded by TBL (guaranteed termination).
__device__ __forceinline__ void lookup_add(int e, int y,
                                           const int2* __restrict__ stab) {
    unsigned s = hash_ent(e) & TBLM;
    #pragma unroll 1
    for (int p = 0; p < TBL; p++) {
        int2 kv = stab[s];                  // one LDS.64: key + val
        if (kv.x == e) { atomicAdd(&g_Mq[kv.y * RR + y], 1); return; }
        if (kv.x == EMPTY_KEY) return;
        s = (s + 1) & TBLM;
    }
}

__device__ __forceinline__ void process_edge(int h, int t, int y,
                                             const int2* __restrict__ stab,
                                             int* __restrict__ shist) {
    atomicAdd(&shist[y], 1);
    lookup_add(h, y, stab);
    if (t != h) lookup_add(t, y, stab);     // self-loop counted once
}

__global__ __launch_bounds__(256) void k_edges(const int* __restrict__ heads,
                                               const int* __restrict__ tails,
                                               const int* __restrict__ types,
                                               const int* __restrict__ qent,
                                               int B, int E) {
    __shared__ int2 stab[TBL];              // (key, val) pairs, 8 KB
    __shared__ int  shist[RR];
    int tid = threadIdx.x;
    for (int j = tid; j < TBL; j += 256) stab[j] = make_int2(EMPTY_KEY, 0x7FFFFFFF);
    for (int j = tid; j < RR; j += 256) shist[j] = 0;
    __syncthreads();
    // build hash from qent (parallel CASes on key, min on val); bounded probes
    for (int q = tid; q < B; q += 256) {
        int ent = qent[q];
        unsigned s = hash_ent(ent) & TBLM;
        #pragma unroll 1
        for (int p = 0; p < TBL; p++) {
            int prev = atomicCAS(&stab[s].x, EMPTY_KEY, ent);
            if (prev == EMPTY_KEY || prev == ent) {
                atomicMin(&stab[s].y, q);   // representative = min b
                break;
            }
            s = (s + 1) & TBLM;
        }
    }
    __syncthreads();

    const int4* h4 = (const int4*)heads;
    const int4* t4 = (const int4*)tails;
    const int4* y4 = (const int4*)types;
    int E4 = E >> 2;
    int gid = blockIdx.x * blockDim.x + tid;
    int stride = gridDim.x * blockDim.x;
    // unroll 2 int4-groups per iteration for MLP + less loop overhead
    int i = gid;
    for (; i + stride < E4; i += 2 * stride) {
        int4 ha = h4[i];          int4 hb = h4[i + stride];
        int4 ta = t4[i];          int4 tb = t4[i + stride];
        int4 ya = y4[i];          int4 yb = y4[i + stride];
        process_edge(ha.x, ta.x, ya.x, stab, shist);
        process_edge(ha.y, ta.y, ya.y, stab, shist);
        process_edge(ha.z, ta.z, ya.z, stab, shist);
        process_edge(ha.w, ta.w, ya.w, stab, shist);
        process_edge(hb.x, tb.x, yb.x, stab, shist);
        process_edge(hb.y, tb.y, yb.y, stab, shist);
        process_edge(hb.z, tb.z, yb.z, stab, shist);
        process_edge(hb.w, tb.w, yb.w, stab, shist);
    }
    if (i < E4) {
        int4 h = h4[i]; int4 t = t4[i]; int4 y = y4[i];
        process_edge(h.x, t.x, y.x, stab, shist);
        process_edge(h.y, t.y, y.y, stab, shist);
        process_edge(h.z, t.z, y.z, stab, shist);
        process_edge(h.w, t.w, y.w, stab, shist);
    }
    if (blockIdx.x == 0 && tid < (E & 3)) {
        int e = (E4 << 2) + tid;
        process_edge(heads[e], tails[e], types[e], stab, shist);
    }
    __syncthreads();
    for (int j = tid; j < RR; j += 256) {
        int v = shist[j];
        if (v) atomicAdd(&g_relc[j], v);
    }
}

// ---------------------------------------------------------------- fused epilogue
// One block of 1024 threads per b: rep scan + Mq row -> deg + gather
// (16 chunks x 64 d) -> fixed-order reduce -> MLP.
__global__ __launch_bounds__(1024) void k_fuse(
    const float* __restrict__ rel_emb,   // [B, R, D]
    const int* __restrict__ qrels,
    const int* __restrict__ qent,
    const float* __restrict__ W1, const float* __restrict__ b1,
    const float* __restrict__ W2, const float* __restrict__ b2,
    const float* __restrict__ W3, const float* __restrict__ b3,
    const float* __restrict__ W4, const float* __restrict__ b4,
    float* __restrict__ out, int B, int E, float density) {
    int b = blockIdx.x;
    int tid = threadIdx.x;
    int lane = tid & 31;

    __shared__ float scnt[RR];
    __shared__ float spart[NCHUNK * DD];
    __shared__ float sx[DIN];
    __shared__ float sw[2][DD];
    __shared__ float sh1[DD];
    __shared__ float sh2[32];
    __shared__ float sg[16];
    __shared__ int sdeg;
    __shared__ int srep;

    if (tid == 0) { sdeg = 0; srep = 0x7FFFFFFF; }
    __syncthreads();
    // rep = min j with qent[j] == qent[b]  (deterministic, direct scan)
    int myent = qent[b];
    if (tid < B && qent[tid] == myent) atomicMin(&srep, tid);
    __syncthreads();
    int rep = srep;
    int qr = qrels[b];

    if (tid < RR) {
        int c = g_Mq[rep * RR + tid];
        scnt[tid] = (float)c;
        #pragma unroll
        for (int o = 16; o; o >>= 1) c += __shfl_down_sync(0xffffffffu, c, o);
        if (lane == 0) atomicAdd(&sdeg, c); // integer: deterministic
    }
    __syncthreads();

    // gather: chunk = tid>>6 handles r in [chunk*32, chunk*32+32)
    {
        int d = tid & 63;
        int ch = tid >> 6;
        const float* base = rel_emb + (size_t)b * RR * DD + d;
        float acc = 0.f;
        #pragma unroll
        for (int j = 0; j < 32; j++) {
            int r = ch * 32 + j;
            float cw = scnt[r];             // uniform across the 64-thread group
            if (cw != 0.0f) acc = fmaf(cw, base[(size_t)r * DD], acc);
        }
        spart[ch * DD + d] = acc;
    }

    float deg = (float)sdeg;
    float inv = 1.0f / fmaxf(deg, 1.0f);
    if (tid < DD)
        sx[tid] = rel_emb[((size_t)b * RR + qr) * DD + tid];
    __syncthreads();
    if (tid < DD) {
        const float* p = spart + tid;
        float s = 0.f;
        #pragma unroll
        for (int c = 0; c < NCHUNK; c++) s += p[c * DD];   // fixed order
        sx[DD + tid] = s * inv;
    }
    if (tid == 0) {
        float freq = fminf((float)g_relc[qr] / (float)E, 1.0f);
        float degn = fminf(deg / (float)E, 1.0f);
        sx[128] = freq;
        sx[129] = degn;
        sx[130] = freq;
        sx[131] = density;
    }
    __syncthreads();

    // W1: 132 -> 64, input range split across 2 half-groups, 4 accs each
    if (tid < 128) {
        int o = tid & 63;
        int h = tid >> 6;
        int i0 = h * 66;
        float a0 = 0.f, a1 = 0.f, a2 = 0.f, a3 = 0.f;
        const float* wcol = W1 + o;
        #pragma unroll
        for (int i = 0; i < 64; i += 4) {
            a0 = fmaf(sx[i0 + i],     wcol[(i0 + i) * 64],     a0);
            a1 = fmaf(sx[i0 + i + 1], wcol[(i0 + i + 1) * 64], a1);
            a2 = fmaf(sx[i0 + i + 2], wcol[(i0 + i + 2) * 64], a2);
            a3 = fmaf(sx[i0 + i + 3], wcol[(i0 + i + 3) * 64], a3);
        }
        a0 = fmaf(sx[i0 + 64], wcol[(i0 + 64) * 64], a0);
        a1 = fmaf(sx[i0 + 65], wcol[(i0 + 65) * 64], a1);
        sw[h][o] = (a0 + a1) + (a2 + a3);
    }
    __syncthreads();
    if (tid < DD)
        sh1[tid] = fmaxf(b1[tid] + sw[0][tid] + sw[1][tid], 0.0f);
    __syncthreads();
    if (tid < 32) {
        float a0 = b2[tid], a1 = 0.f, a2 = 0.f, a3 = 0.f;
        #pragma unroll
        for (int i = 0; i < 64; i += 4) {
            a0 = fmaf(sh1[i],     W2[i * 32 + tid],       a0);
            a1 = fmaf(sh1[i + 1], W2[(i + 1) * 32 + tid], a1);
            a2 = fmaf(sh1[i + 2], W2[(i + 2) * 32 + tid], a2);
            a3 = fmaf(sh1[i + 3], W2[(i + 3) * 32 + tid], a3);
        }
        sh2[tid] = fmaxf((a0 + a1) + (a2 + a3), 0.0f);
    }
    __syncthreads();
    if (tid < 16) {
        float a0 = b3[tid], a1 = 0.f;
        #pragma unroll
        for (int i = 0; i < 32; i += 2) {
            a0 = fmaf(sh2[i],     W3[i * 16 + tid],       a0);
            a1 = fmaf(sh2[i + 1], W3[(i + 1) * 16 + tid], a1);
        }
        sg[tid] = fmaxf(a0 + a1, 0.0f);
    }
    __syncthreads();
    if (tid == 0) {
        float acc = b4[0];
        #pragma unroll
        for (int i = 0; i < 16; i++) acc = fmaf(sg[i], W4[i], acc);
        out[b] = 1.0f / (1.0f + expf(-acc));
    }
}

// ---------------------------------------------------------------- launch
extern "C" void kernel_launch(void* const* d_in, const int* in_sizes, int n_in,
                              void* d_out, int out_size) {
    const float* rel_emb = (const float*)d_in[0];
    const int*   qrels   = (const int*)d_in[1];
    const int*   qent    = (const int*)d_in[2];
    const int*   eidx    = (const int*)d_in[3];
    const int*   etype   = (const int*)d_in[4];
    const float* W1 = (const float*)d_in[n_in - 8];
    const float* b1 = (const float*)d_in[n_in - 7];
    const float* W2 = (const float*)d_in[n_in - 6];
    const float* b2 = (const float*)d_in[n_in - 5];
    const float* W3 = (const float*)d_in[n_in - 4];
    const float* b3 = (const float*)d_in[n_in - 3];
    const float* W4 = (const float*)d_in[n_in - 2];
    const float* b4 = (const float*)d_in[n_in - 1];

    int B = in_sizes[1];          // 256
    int E = in_sizes[4];          // 3,200,000
    const int* heads = eidx;
    const int* tails = eidx + E;

    double Nd = 100000.0;         // fixed problem
    float density = (float)fmin((double)E / (Nd * Nd), 1.0);

    k_init<<<BB * RR / 4 / 256, 256>>>();
    k_edges<<<EGRID, 256>>>(heads, tails, etype, qent, B, E);
    k_fuse<<<BB, 1024>>>(rel_emb, qrels, qent,
                         W1, b1, W2, b2, W3, b3, W4, b4,
                         (float*)d_out, B, E, density);
}

// round 11
// speedup vs baseline: 2.3368x; 1.5813x over previous
#include <cuda_runtime.h>
#include <math.h>

// Fixed problem shapes (B=256, R=512, D=64, N=100000, E=3.2M)
#define RR   512
#define DD   64
#define BB   256
#define NN   100000
#define NBW  3136         // bitmap words: ceil(100000/32)=3125, padded
#define DIN  132          // 2*DD + 4
#define TBL  1024         // hash table slots (load factor <= 0.25)
#define TBLM (TBL - 1)
#define EMPTY_KEY (-1)
#define NCHUNK 16         // gather chunks (64 threads each) in k_fuse
#define EGRID 592         // edge blocks: 4 per SM (r7-proven)

// Scratch (device globals: no allocation allowed in kernel_launch)
__device__ int g_Mq[BB * RR];     // per-representative-b relation counts
__device__ int g_relc[RR];        // global relation histogram

__device__ __forceinline__ unsigned hash_ent(int x) {
    return ((unsigned)x * 2654435761u) >> 16;
}

// ---------------------------------------------------------------- init
// Pure clear, fully parallel, no serial phases.
__global__ __launch_bounds__(256) void k_init() {
    int gid = blockIdx.x * 256 + threadIdx.x;
    if (gid < BB * RR / 4)
        ((int4*)g_Mq)[gid] = make_int4(0, 0, 0, 0);
    if (gid < RR) g_relc[gid] = 0;
}

// ---------------------------------------------------------------- edge scan
// Fast path: SMEM membership bitmap (1 LDS + bit test per endpoint, branch-
// free). Slow path (rare, ~0.45% of edges): bounded SMEM hash probe for the
// representative b, then a global atomic into g_Mq.
__device__ __forceinline__ void lookup_add(int e, int y,
                                           const int* __restrict__ skeys,
                                           const int* __restrict__ svals) {
    unsigned s = hash_ent(e) & TBLM;
    #pragma unroll 1
    for (int p = 0; p < TBL; p++) {
        int k = skeys[s];
        if (k == e) { atomicAdd(&g_Mq[svals[s] * RR + y], 1); return; }
        if (k == EMPTY_KEY) return;
        s = (s + 1) & TBLM;
    }
}

__device__ __forceinline__ void process_edge(int h, int t, int y,
                                             const unsigned* __restrict__ sbit,
                                             const int* __restrict__ skeys,
                                             const int* __restrict__ svals,
                                             int* __restrict__ shist) {
    atomicAdd(&shist[y], 1);
    bool hh = (sbit[h >> 5] >> (h & 31)) & 1u;
    bool ht = ((sbit[t >> 5] >> (t & 31)) & 1u) && (t != h);  // self-loop once
    if (hh | ht) {                       // rare
        if (hh) lookup_add(h, y, skeys, svals);
        if (ht) lookup_add(t, y, skeys, svals);
    }
}

__global__ __launch_bounds__(256) void k_edges(const int* __restrict__ heads,
                                               const int* __restrict__ tails,
                                               const int* __restrict__ types,
                                               const int* __restrict__ qent,
                                               int B, int E) {
    __shared__ unsigned sbit[NBW];          // 12.25 KB membership bitmap
    __shared__ int skeys[TBL];              // 4 KB
    __shared__ int svals[TBL];              // 4 KB
    __shared__ int shist[RR];               // 2 KB
    int tid = threadIdx.x;
    for (int j = tid; j < NBW; j += 256) sbit[j] = 0u;
    for (int j = tid; j < TBL; j += 256) { skeys[j] = EMPTY_KEY; svals[j] = 0x7FFFFFFF; }
    for (int j = tid; j < RR; j += 256) shist[j] = 0;
    __syncthreads();
    // build bitmap + hash from qent (dedup via min-b); bounded probes
    for (int q = tid; q < B; q += 256) {
        int ent = qent[q];
        atomicOr(&sbit[ent >> 5], 1u << (ent & 31));
        unsigned s = hash_ent(ent) & TBLM;
        #pragma unroll 1
        for (int p = 0; p < TBL; p++) {
            int prev = atomicCAS(&skeys[s], EMPTY_KEY, ent);
            if (prev == EMPTY_KEY || prev == ent) {
                atomicMin(&svals[s], q);    // representative = min b
                break;
            }
            s = (s + 1) & TBLM;
        }
    }
    __syncthreads();

    const int4* h4 = (const int4*)heads;
    const int4* t4 = (const int4*)tails;
    const int4* y4 = (const int4*)types;
    int E4 = E >> 2;
    int gid = blockIdx.x * blockDim.x + tid;
    int stride = gridDim.x * blockDim.x;
    for (int i = gid; i < E4; i += stride) {
        int4 h = h4[i];
        int4 t = t4[i];
        int4 y = y4[i];
        process_edge(h.x, t.x, y.x, sbit, skeys, svals, shist);
        process_edge(h.y, t.y, y.y, sbit, skeys, svals, shist);
        process_edge(h.z, t.z, y.z, sbit, skeys, svals, shist);
        process_edge(h.w, t.w, y.w, sbit, skeys, svals, shist);
    }
    if (blockIdx.x == 0 && tid < (E & 3)) {
        int e = (E4 << 2) + tid;
        process_edge(heads[e], tails[e], types[e], sbit, skeys, svals, shist);
    }
    __syncthreads();
    for (int j = tid; j < RR; j += 256) {
        int v = shist[j];
        if (v) atomicAdd(&g_relc[j], v);
    }
}

// ---------------------------------------------------------------- fused epilogue
// One block of 1024 threads per b: rep scan + Mq row -> deg + gather
// (16 chunks x 64 d) -> fixed-order reduce -> MLP.
__global__ __launch_bounds__(1024) void k_fuse(
    const float* __restrict__ rel_emb,   // [B, R, D]
    const int* __restrict__ qrels,
    const int* __restrict__ qent,
    const float* __restrict__ W1, const float* __restrict__ b1,
    const float* __restrict__ W2, const float* __restrict__ b2,
    const float* __restrict__ W3, const float* __restrict__ b3,
    const float* __restrict__ W4, const float* __restrict__ b4,
    float* __restrict__ out, int B, int E, float density) {
    int b = blockIdx.x;
    int tid = threadIdx.x;
    int lane = tid & 31;

    __shared__ float scnt[RR];
    __shared__ float spart[NCHUNK * DD];
    __shared__ float sx[DIN];
    __shared__ float sw[2][DD];
    __shared__ float sh1[DD];
    __shared__ float sh2[32];
    __shared__ float sg[16];
    __shared__ int sdeg;
    __shared__ int srep;

    if (tid == 0) { sdeg = 0; srep = 0x7FFFFFFF; }
    __syncthreads();
    // rep = min j with qent[j] == qent[b]  (deterministic, direct scan)
    int myent = qent[b];
    if (tid < B && qent[tid] == myent) atomicMin(&srep, tid);
    __syncthreads();
    int rep = srep;
    int qr = qrels[b];

    if (tid < RR) {
        int c = g_Mq[rep * RR + tid];
        scnt[tid] = (float)c;
        #pragma unroll
        for (int o = 16; o; o >>= 1) c += __shfl_down_sync(0xffffffffu, c, o);
        if (lane == 0) atomicAdd(&sdeg, c); // integer: deterministic
    }
    __syncthreads();

    // gather: chunk = tid>>6 handles r in [chunk*32, chunk*32+32)
    {
        int d = tid & 63;
        int ch = tid >> 6;
        const float* base = rel_emb + (size_t)b * RR * DD + d;
        float acc = 0.f;
        #pragma unroll
        for (int j = 0; j < 32; j++) {
            int r = ch * 32 + j;
            float cw = scnt[r];             // uniform across the 64-thread group
            if (cw != 0.0f) acc = fmaf(cw, base[(size_t)r * DD], acc);
        }
        spart[ch * DD + d] = acc;
    }

    float deg = (float)sdeg;
    float inv = 1.0f / fmaxf(deg, 1.0f);
    if (tid < DD)
        sx[tid] = rel_emb[((size_t)b * RR + qr) * DD + tid];
    __syncthreads();
    if (tid < DD) {
        const float* p = spart + tid;
        float s = 0.f;
        #pragma unroll
        for (int c = 0; c < NCHUNK; c++) s += p[c * DD];   // fixed order
        sx[DD + tid] = s * inv;
    }
    if (tid == 0) {
        float freq = fminf((float)g_relc[qr] / (float)E, 1.0f);
        float degn = fminf(deg / (float)E, 1.0f);
        sx[128] = freq;
        sx[129] = degn;
        sx[130] = freq;
        sx[131] = density;
    }
    __syncthreads();

    // W1: 132 -> 64, input range split across 2 half-groups, 4 accs each
    if (tid < 128) {
        int o = tid & 63;
        int h = tid >> 6;
        int i0 = h * 66;
        float a0 = 0.f, a1 = 0.f, a2 = 0.f, a3 = 0.f;
        const float* wcol = W1 + o;
        #pragma unroll
        for (int i = 0; i < 64; i += 4) {
            a0 = fmaf(sx[i0 + i],     wcol[(i0 + i) * 64],     a0);
            a1 = fmaf(sx[i0 + i + 1], wcol[(i0 + i + 1) * 64], a1);
            a2 = fmaf(sx[i0 + i + 2], wcol[(i0 + i + 2) * 64], a2);
            a3 = fmaf(sx[i0 + i + 3], wcol[(i0 + i + 3) * 64], a3);
        }
        a0 = fmaf(sx[i0 + 64], wcol[(i0 + 64) * 64], a0);
        a1 = fmaf(sx[i0 + 65], wcol[(i0 + 65) * 64], a1);
        sw[h][o] = (a0 + a1) + (a2 + a3);
    }
    __syncthreads();
    if (tid < DD)
        sh1[tid] = fmaxf(b1[tid] + sw[0][tid] + sw[1][tid], 0.0f);
    __syncthreads();
    if (tid < 32) {
        float a0 = b2[tid], a1 = 0.f, a2 = 0.f, a3 = 0.f;
        #pragma unroll
        for (int i = 0; i < 64; i += 4) {
            a0 = fmaf(sh1[i],     W2[i * 32 + tid],       a0);
            a1 = fmaf(sh1[i + 1], W2[(i + 1) * 32 + tid], a1);
            a2 = fmaf(sh1[i + 2], W2[(i + 2) * 32 + tid], a2);
            a3 = fmaf(sh1[i + 3], W2[(i + 3) * 32 + tid], a3);
        }
        sh2[tid] = fmaxf((a0 + a1) + (a2 + a3), 0.0f);
    }
    __syncthreads();
    if (tid < 16) {
        float a0 = b3[tid], a1 = 0.f;
        #pragma unroll
        for (int i = 0; i < 32; i += 2) {
            a0 = fmaf(sh2[i],     W3[i * 16 + tid],       a0);
            a1 = fmaf(sh2[i + 1], W3[(i + 1) * 16 + tid], a1);
        }
        sg[tid] = fmaxf(a0 + a1, 0.0f);
    }
    __syncthreads();
    if (tid == 0) {
        float acc = b4[0];
        #pragma unroll
        for (int i = 0; i < 16; i++) acc = fmaf(sg[i], W4[i], acc);
        out[b] = 1.0f / (1.0f + expf(-acc));
    }
}

// ---------------------------------------------------------------- launch
extern "C" void kernel_launch(void* const* d_in, const int* in_sizes, int n_in,
                              void* d_out, int out_size) {
    const float* rel_emb = (const float*)d_in[0];
    const int*   qrels   = (const int*)d_in[1];
    const int*   qent    = (const int*)d_in[2];
    const int*   eidx    = (const int*)d_in[3];
    const int*   etype   = (const int*)d_in[4];
    const float* W1 = (const float*)d_in[n_in - 8];
    const float* b1 = (const float*)d_in[n_in - 7];
    const float* W2 = (const float*)d_in[n_in - 6];
    const float* b2 = (const float*)d_in[n_in - 5];
    const float* W3 = (const float*)d_in[n_in - 4];
    const float* b3 = (const float*)d_in[n_in - 3];
    const float* W4 = (const float*)d_in[n_in - 2];
    const float* b4 = (const float*)d_in[n_in - 1];

    int B = in_sizes[1];          // 256
    int E = in_sizes[4];          // 3,200,000
    const int* heads = eidx;
    const int* tails = eidx + E;

    double Nd = (double)NN;       // fixed problem
    float density = (float)fmin((double)E / (Nd * Nd), 1.0);

    k_init<<<BB * RR / 4 / 256, 256>>>();
    k_edges<<<EGRID, 256>>>(heads, tails, etype, qent, B, E);
    k_fuse<<<BB, 1024>>>(rel_emb, qrels, qent,
                         W1, b1, W2, b2, W3, b3, W4, b4,
                         (float*)d_out, B, E, density);
}